// round 7
// baseline (speedup 1.0000x reference)
#include <cuda_runtime.h>
#include <cuda_fp16.h>
#include <math.h>

// Problem constants
#define Bv   2
#define Cc   256
#define Nt   32768      // D*H*W
#define Ss   256
#define TDv  512
#define NHh  8
#define HDd  32
#define SCALE 0.17677669529663687f   // 1/sqrt(32)

// Scratch (device globals — allocation-free rule)
__device__ __half   g_qh[(size_t)Bv * Nt * Cc];     // q post-RoPE, pre-scaled, fp16
__device__ __half   g_fvh[(size_t)Bv * Nt * Cc];    // fv TRANSPOSED [b][m][k], fp16
__device__ float    g_attn[(size_t)Bv * Nt * Cc];   // attention output per token
__device__ __half   g_kh[Bv * NHh * Ss * HDd];      // k_rot fp16 [bh][s][d]
__device__ __half   g_vh[Bv * NHh * Ss * HDd];      // pair-interleaved [bh][s2][d][2]
__device__ float2   g_cs[1024];                     // cos/sin table [pos][hd]
__device__ __half   g_qwh[Cc * Cc];                 // q_w fp16 TRANSPOSED [n][k]
__device__ unsigned g_ow[Cc * Cc];                  // o_w tf32-rna TRANSPOSED [n][k]

// ---------------------------------------------------------------------------
// helpers
// ---------------------------------------------------------------------------
__device__ __forceinline__ unsigned f2tf(float f) {
    unsigned r;
    asm("cvt.rna.tf32.f32 %0, %1;" : "=r"(r) : "f"(f));
    return r;
}
__device__ __forceinline__ void mma8(float* d, const unsigned* a, const unsigned* b) {
    asm volatile(
        "mma.sync.aligned.m16n8k8.row.col.f32.tf32.tf32.f32 "
        "{%0,%1,%2,%3}, {%4,%5,%6,%7}, {%8,%9}, {%0,%1,%2,%3};"
        : "+f"(d[0]), "+f"(d[1]), "+f"(d[2]), "+f"(d[3])
        : "r"(a[0]), "r"(a[1]), "r"(a[2]), "r"(a[3]), "r"(b[0]), "r"(b[1]));
}
__device__ __forceinline__ void mma16h(float* d, const unsigned* a, unsigned b0, unsigned b1) {
    asm volatile(
        "mma.sync.aligned.m16n8k16.row.col.f32.f16.f16.f32 "
        "{%0,%1,%2,%3}, {%4,%5,%6,%7}, {%8,%9}, {%0,%1,%2,%3};"
        : "+f"(d[0]), "+f"(d[1]), "+f"(d[2]), "+f"(d[3])
        : "r"(a[0]), "r"(a[1]), "r"(a[2]), "r"(a[3]), "r"(b0), "r"(b1));
}
__device__ __forceinline__ void ldsm4(unsigned* r, unsigned addr) {
    asm volatile("ldmatrix.sync.aligned.m8n8.x4.shared.b16 {%0,%1,%2,%3}, [%4];"
        : "=r"(r[0]), "=r"(r[1]), "=r"(r[2]), "=r"(r[3]) : "r"(addr));
}
__device__ __forceinline__ unsigned packh2(float lo, float hi) {
    __half2 h = __floats2half2_rn(lo, hi);
    return *reinterpret_cast<unsigned*>(&h);
}
__device__ __forceinline__ unsigned saddr(const void* p) {
    return (unsigned)__cvta_generic_to_shared(p);
}
__device__ __forceinline__ void cpa16(unsigned s, const void* g) {
    asm volatile("cp.async.cg.shared.global [%0], [%1], 16;\n" :: "r"(s), "l"(g));
}
#define CPC() asm volatile("cp.async.commit_group;\n" ::)
#define CPW(n) asm volatile("cp.async.wait_group %0;\n" :: "n"(n))

// ---------------------------------------------------------------------------
// Prep (ONE launch): fv transpose fp32[b][k][m] -> fp16 [b][m][k],
// weight conversions, RoPE cos/sin table.
// grid (1024, 8, 2), 256 threads: 32x32 tile transpose per block.
// ---------------------------------------------------------------------------
__global__ __launch_bounds__(256) void k_prep(
    const float* __restrict__ qw, const float* __restrict__ ow,
    const float* __restrict__ fv)
{
    __shared__ __half sm[32][33];
    const int m0 = blockIdx.x * 32, k0 = blockIdx.y * 32, b = blockIdx.z;
    const int t = threadIdx.x;

    int kr = t >> 3, mc = (t & 7) * 4;
    float4 v = *(const float4*)(fv + ((size_t)b * Cc + k0 + kr) * Nt + m0 + mc);
    sm[kr][mc + 0] = __float2half(v.x);
    sm[kr][mc + 1] = __float2half(v.y);
    sm[kr][mc + 2] = __float2half(v.z);
    sm[kr][mc + 3] = __float2half(v.w);
    __syncthreads();

    int mr = t >> 3, kc = (t & 7) * 4;
    __half2 p0 = __halves2half2(sm[kc + 0][mr], sm[kc + 1][mr]);
    __half2 p1 = __halves2half2(sm[kc + 2][mr], sm[kc + 3][mr]);
    __half2* dst = (__half2*)(g_fvh + ((size_t)b * Nt + m0 + mr) * Cc + k0 + kc);
    dst[0] = p0;
    dst[1] = p1;

    // side work: weights (transposed) + table
    if (b == 0 && blockIdx.y == 0 && blockIdx.x < 256) {
        int i = blockIdx.x * 256 + t;          // 65536
        int n = i >> 8, k = i & 255;
        g_qwh[i] = __float2half(qw[k * 256 + n]);
        g_ow[i]  = f2tf(ow[k * 256 + n]);
    }
    if (b == 1 && blockIdx.y == 0 && blockIdx.x < 4) {
        int i = blockIdx.x * 256 + t;          // 0..1023
        int pos = i >> 5, hd = i & 31;
        float ex;
        if (hd < 10)       ex = (float)(hd % 5) * 0.2f;
        else if (hd < 20)  ex = (float)((hd - 10) % 5) * 0.2f;
        else               ex = (float)((hd - 20) % 6) * (1.0f / 6.0f);
        float invf = powf(10000.0f, -ex);
        float f = (float)pos * invf;
        float c, s;
        sincosf(f, &s, &c);
        g_cs[i] = make_float2(c, s);
    }
}

// ---------------------------------------------------------------------------
// Text side: 8 tokens per block (64 blocks).
// ---------------------------------------------------------------------------
__global__ __launch_bounds__(256) void k_text(
    const float* __restrict__ text,
    const float* __restrict__ k_w, const float* __restrict__ k_b,
    const float* __restrict__ v_w, const float* __restrict__ v_b,
    const float* __restrict__ m1_w, const float* __restrict__ m1_b,
    const float* __restrict__ m2_w, const float* __restrict__ m2_b)
{
    __shared__ float tx8[8][TDv];
    __shared__ float hbuf8[8][Cc];
    __shared__ float kbuf8[8][Cc];
    const int t0 = blockIdx.x * 8;
    const int b = t0 >> 8;
    const int t = threadIdx.x;

    for (int i = t; i < 8 * TDv; i += 256) {
        int r = i >> 9, c = i & 511;
        tx8[r][c] = text[(size_t)(t0 + r) * TDv + c];
    }
    __syncthreads();

    float kv[8], vv[8], hv[8];
    float kb0 = k_b[t], vb0 = v_b[t], mb0 = m1_b[t];
    #pragma unroll
    for (int r = 0; r < 8; r++) { kv[r] = kb0; vv[r] = vb0; hv[r] = mb0; }

    #pragma unroll 4
    for (int j = 0; j < TDv; j++) {
        float kwj = k_w[j * Cc + t];
        float vwj = v_w[j * Cc + t];
        float mwj = m1_w[j * Cc + t];
        #pragma unroll
        for (int r = 0; r < 8; r++) {
            float x = tx8[r][j];
            kv[r] += x * kwj;
            vv[r] += x * vwj;
            hv[r] += x * mwj;
        }
    }
    const int head = t >> 5, hd = t & 31;
    const int bh = b * NHh + head;
    #pragma unroll
    for (int r = 0; r < 8; r++) {
        hv[r] = 0.5f * hv[r] * (1.0f + erff(hv[r] * 0.70710678118654752f));
        kbuf8[r][t] = kv[r];
        hbuf8[r][t] = hv[r];
        int s = (t0 + r) & 255;
        g_vh[(((size_t)bh * 128 + (s >> 1)) * 32 + hd) * 2 + (s & 1)] = __float2half(vv[r]);
    }
    __syncthreads();

    float ph[8];
    float pb0 = m2_b[t];
    #pragma unroll
    for (int r = 0; r < 8; r++) ph[r] = pb0;
    #pragma unroll 4
    for (int j = 0; j < Cc; j++) {
        float mw = m2_w[j * Cc + t];
        #pragma unroll
        for (int r = 0; r < 8; r++) ph[r] += hbuf8[r][j] * mw;
    }
    #pragma unroll
    for (int r = 0; r < 8; r++) {
        float c, sn;
        sincosf(ph[r], &sn, &c);
        float other = (hd < 16) ? -kbuf8[r][head * 32 + hd + 16]
                                :  kbuf8[r][head * 32 + hd - 16];
        float kr = kv[r] * c + other * sn;
        int s = (t0 + r) & 255;
        g_kh[((size_t)bh * Ss + s) * HDd + hd] = __float2half(kr);
    }
}

// ---------------------------------------------------------------------------
// Q projection: FP16 mma (m16n8k16), cp.async double-buffered,
// bias + RoPE + SCALE epilogue, fp16 output. Only feeds logits -> fp16 safe.
// As [m 128][k 40 halves pad], Bs [n 128][k 40] per buffer.
// ---------------------------------------------------------------------------
__global__ __launch_bounds__(256, 2) void k_qproj(const float* __restrict__ bias)
{
    extern __shared__ __half smqh[];
    // layout: As buf0 | As buf1 | Bs buf0 | Bs buf1, each 128*40 halves
    const int b = blockIdx.z;
    const int m0 = blockIdx.x * 128;
    const int n0 = blockIdx.y * 128;
    const int tid = threadIdx.x;
    const int wid = tid >> 5, lane = tid & 31;
    const int q = lane & 3, g = lane >> 2;
    const int wm = wid >> 1, wn = wid & 1;

    float acc[2][8][4];
    #pragma unroll
    for (int a = 0; a < 2; a++)
        #pragma unroll
        for (int j = 0; j < 8; j++)
            #pragma unroll
            for (int r = 0; r < 4; r++) acc[a][j][r] = 0.f;

    const __half* Ag = g_fvh + ((size_t)b * Nt + m0) * Cc;
    const __half* Bg = g_qwh + (size_t)n0 * Cc;

    // tile fill: 128 rows x 32 halves (64B) per matrix; 16B per thread x2 iters
    {
        #pragma unroll
        for (int i = 0; i < 2; i++) {
            int c = tid + i * 256;
            int row = c >> 2, off = (c & 3) * 8;
            cpa16(saddr(smqh + row * 40 + off), Ag + (size_t)row * Cc + off);
            cpa16(saddr(smqh + 10240 + row * 40 + off), Bg + (size_t)row * Cc + off);
        }
        CPC();
    }
    for (int it = 0; it < 8; it++) {
        if (it < 7) {
            int k0 = (it + 1) * 32;
            int buf = (it + 1) & 1;
            #pragma unroll
            for (int i = 0; i < 2; i++) {
                int c = tid + i * 256;
                int row = c >> 2, off = (c & 3) * 8;
                cpa16(saddr(smqh + buf * 5120 + row * 40 + off),
                      Ag + (size_t)row * Cc + k0 + off);
                cpa16(saddr(smqh + 10240 + buf * 5120 + row * 40 + off),
                      Bg + (size_t)row * Cc + k0 + off);
            }
            CPC();
            CPW(1);
        } else {
            CPW(0);
        }
        __syncthreads();
        const unsigned* as32 = (const unsigned*)(smqh + (it & 1) * 5120);
        const unsigned* bs32 = (const unsigned*)(smqh + 10240 + (it & 1) * 5120);
        #pragma unroll
        for (int kc = 0; kc < 2; kc++) {
            unsigned af[2][4];
            #pragma unroll
            for (int mi = 0; mi < 2; mi++) {
                int row = wm * 32 + mi * 16 + g;
                af[mi][0] = as32[row * 20 + kc * 8 + q];
                af[mi][1] = as32[(row + 8) * 20 + kc * 8 + q];
                af[mi][2] = as32[row * 20 + kc * 8 + q + 4];
                af[mi][3] = as32[(row + 8) * 20 + kc * 8 + q + 4];
            }
            #pragma unroll
            for (int nj = 0; nj < 8; nj++) {
                int col = wn * 64 + nj * 8 + g;
                unsigned b0 = bs32[col * 20 + kc * 8 + q];
                unsigned b1 = bs32[col * 20 + kc * 8 + q + 4];
                mma16h(acc[0][nj], af[0], b0, b1);
                mma16h(acc[1][nj], af[1], b0, b1);
            }
        }
        __syncthreads();
    }
    // stage cos/sin table into now-dead smem
    float2* css = (float2*)smqh;
    for (int i = tid; i < 1024; i += 256) css[i] = g_cs[i];
    __syncthreads();
    // epilogue: bias + RoPE + SCALE + fp16 store
    unsigned* qo = (unsigned*)g_qh;
    #pragma unroll
    for (int mi = 0; mi < 2; mi++) {
        #pragma unroll
        for (int half = 0; half < 2; half++) {
            int m = m0 + wm * 32 + mi * 16 + g + half * 8;
            int d = m >> 10, hh = (m >> 5) & 31, wc = m & 31;
            float vals[8][2];
            #pragma unroll
            for (int nj = 0; nj < 8; nj++) {
                int col = n0 + wn * 64 + nj * 8 + 2 * q;
                vals[nj][0] = acc[mi][nj][half * 2 + 0] + bias[col];
                vals[nj][1] = acc[mi][nj][half * 2 + 1] + bias[col + 1];
            }
            unsigned* orow = qo + ((size_t)b * Nt + m) * (Cc / 2);
            #pragma unroll
            for (int nj = 0; nj < 8; nj++) {
                float o2[2];
                #pragma unroll
                for (int e = 0; e < 2; e++) {
                    int hd = (nj & 3) * 8 + 2 * q + e;
                    bool lo = hd < 16;
                    int pos = lo ? ((hd < 10) ? d : hh) : ((hd < 20) ? hh : wc);
                    float2 cs = css[pos * 32 + hd];
                    float partner = lo ? vals[nj + 2][e] : vals[nj - 2][e];
                    float r = lo ? vals[nj][e] * cs.x - partner * cs.y
                                 : vals[nj][e] * cs.x + partner * cs.y;
                    o2[e] = r * SCALE;
                }
                int col = n0 + wn * 64 + nj * 8 + 2 * q;
                orow[col >> 1] = packh2(o2[0], o2[1]);
            }
        }
    }
}

// ---------------------------------------------------------------------------
// Fused attention, all-fp16 tensor path. (launch index 3 -> ncu target)
// ---------------------------------------------------------------------------
__global__ __launch_bounds__(256, 3) void k_fattn() {
    extern __shared__ unsigned sm[];
    unsigned* Ksh = sm;                // 256*20
    unsigned* Vs  = sm + 256 * 20;     // 128*40
    const int bh = blockIdx.y;
    const int b = bh >> 3, h = bh & 7;
    const int m0 = blockIdx.x * 128;
    const int tid = threadIdx.x, wid = tid >> 5, lane = tid & 31;
    const int q = lane & 3, g = lane >> 2;

    const unsigned* kph = (const unsigned*)g_kh + (size_t)bh * 256 * 16;
    const unsigned* vph = (const unsigned*)g_vh + (size_t)bh * 128 * 32;
    for (int i = tid; i < 256 * 16; i += 256) {
        int s = i >> 4, d2 = i & 15;
        Ksh[s * 20 + d2] = kph[i];
    }
    for (int i = tid; i < 128 * 32; i += 256) {
        int s2 = i >> 5, d = i & 31;
        Vs[s2 * 40 + d] = vph[i];
    }
    const unsigned* qrow = (const unsigned*)g_qh
                         + ((size_t)b * Nt + m0 + wid * 16) * (Cc / 2) + h * 16;
    unsigned qf[2][4];
    #pragma unroll
    for (int ks = 0; ks < 2; ks++) {
        qf[ks][0] = qrow[(size_t)g * 128 + ks * 8 + q];
        qf[ks][1] = qrow[(size_t)(g + 8) * 128 + ks * 8 + q];
        qf[ks][2] = qrow[(size_t)g * 128 + ks * 8 + q + 4];
        qf[ks][3] = qrow[(size_t)(g + 8) * 128 + ks * 8 + q + 4];
    }
    __syncthreads();

    float o[4][4];
    #pragma unroll
    for (int i = 0; i < 4; i++)
        #pragma unroll
        for (int r = 0; r < 4; r++) o[i][r] = 0.f;
    float l_lo = 0.f, l_hi = 0.f;

    #pragma unroll
    for (int ch = 0; ch < 8; ch++) {
        float s[4][4];
        #pragma unroll
        for (int t = 0; t < 4; t++)
            #pragma unroll
            for (int r = 0; r < 4; r++) s[t][r] = 0.f;
        #pragma unroll
        for (int ks = 0; ks < 2; ks++) {
            #pragma unroll
            for (int nt = 0; nt < 4; nt++) {
                int key = ch * 32 + nt * 8 + g;
                unsigned b0 = Ksh[key * 20 + ks * 8 + q];
                unsigned b1 = Ksh[key * 20 + ks * 8 + q + 4];
                mma16h(s[nt], qf[ks], b0, b1);
            }
        }
        unsigned pa[4][2];
        #pragma unroll
        for (int st = 0; st < 4; st++) {
            float e0 = __expf(s[st][0]), e1 = __expf(s[st][1]);
            float e2 = __expf(s[st][2]), e3 = __expf(s[st][3]);
            l_lo += e0 + e1;
            l_hi += e2 + e3;
            pa[st][0] = packh2(e0, e1);
            pa[st][1] = packh2(e2, e3);
        }
        #pragma unroll
        for (int kt = 0; kt < 2; kt++) {
            unsigned Af[4] = { pa[2 * kt][0], pa[2 * kt][1],
                               pa[2 * kt + 1][0], pa[2 * kt + 1][1] };
            int s2b = ch * 16 + kt * 8 + q;
            #pragma unroll
            for (int nt = 0; nt < 4; nt++) {
                mma16h(o[nt], Af, Vs[s2b * 40 + nt * 8 + g],
                                  Vs[(s2b + 4) * 40 + nt * 8 + g]);
            }
        }
    }
    l_lo += __shfl_xor_sync(0xffffffffu, l_lo, 1);
    l_lo += __shfl_xor_sync(0xffffffffu, l_lo, 2);
    l_hi += __shfl_xor_sync(0xffffffffu, l_hi, 1);
    l_hi += __shfl_xor_sync(0xffffffffu, l_hi, 2);
    float il = 1.0f / l_lo, ih = 1.0f / l_hi;

    float* op  = g_attn + ((size_t)b * Nt + m0 + wid * 16 + g) * Cc + h * 32;
    float* op2 = op + 8 * Cc;
    #pragma unroll
    for (int nt = 0; nt < 4; nt++) {
        *(float2*)(op  + nt * 8 + 2 * q) = make_float2(o[nt][0] * il, o[nt][1] * il);
        *(float2*)(op2 + nt * 8 + 2 * q) = make_float2(o[nt][2] * ih, o[nt][3] * ih);
    }
}

// ---------------------------------------------------------------------------
// O projection (tf32 mma, cp.async, full-ldmatrix) + bias + transposed store.
// ---------------------------------------------------------------------------
__global__ __launch_bounds__(256, 2) void k_oproj(
    const float* __restrict__ bias, float* __restrict__ out)
{
    extern __shared__ unsigned smo[];
    unsigned* As = smo;                    // 2 * 128*36
    unsigned* Bs = smo + 2 * 128 * 36;     // 2 * 128*36
    const int b = blockIdx.z;
    const int m0 = blockIdx.x * 128;
    const int n0 = blockIdx.y * 128;
    const int tid = threadIdx.x;
    const int wid = tid >> 5, lane = tid & 31;
    const int q = lane & 3, g = lane >> 2;
    const int wm = wid >> 1, wn = wid & 1;
    const int t4 = lane >> 3;

    const unsigned aq_base = saddr(As) + ((wm * 32 + ((t4 & 1) << 3) + (lane & 7)) * 36
                                          + (t4 >> 1) * 4) * 4;
    const unsigned bq_base = saddr(Bs) + ((wn * 64 + ((t4 >> 1) << 3) + (lane & 7)) * 36
                                          + (t4 & 1) * 4) * 4;

    float acc[2][8][4];
    #pragma unroll
    for (int a = 0; a < 2; a++)
        #pragma unroll
        for (int j = 0; j < 8; j++)
            #pragma unroll
            for (int r = 0; r < 4; r++) acc[a][j][r] = 0.f;

    const float* A = g_attn + (size_t)b * Nt * Cc;
    {
        #pragma unroll
        for (int i = 0; i < 4; i++) {
            int c = tid + i * 256;
            int mm = c >> 3, kkc = (c & 7) * 4;
            cpa16(saddr(&As[mm * 36 + kkc]), A + (size_t)(m0 + mm) * Cc + kkc);
            cpa16(saddr(&Bs[mm * 36 + kkc]), g_ow + (n0 + mm) * 256 + kkc);
        }
        CPC();
    }
    for (int it = 0; it < 8; it++) {
        if (it < 7) {
            int k0 = (it + 1) * 32;
            unsigned off = ((it + 1) & 1) * (128 * 36);
            #pragma unroll
            for (int i = 0; i < 4; i++) {
                int c = tid + i * 256;
                int mm = c >> 3, kkc = (c & 7) * 4;
                cpa16(saddr(&As[off + mm * 36 + kkc]), A + (size_t)(m0 + mm) * Cc + k0 + kkc);
                cpa16(saddr(&Bs[off + mm * 36 + kkc]), g_ow + (n0 + mm) * 256 + k0 + kkc);
            }
            CPC();
            CPW(1);
        } else {
            CPW(0);
        }
        __syncthreads();
        const unsigned bufA = aq_base + (it & 1) * (128 * 36 * 4);
        const unsigned bufB = bq_base + (it & 1) * (128 * 36 * 4);
        #pragma unroll
        for (int kc = 0; kc < 4; kc++) {
            unsigned af[2][4];
            ldsm4(af[0], bufA + (kc * 8) * 4);
            ldsm4(af[1], bufA + (16 * 36 + kc * 8) * 4);
            #pragma unroll
            for (int jj = 0; jj < 4; jj++) {
                unsigned bf[4];
                ldsm4(bf, bufB + (jj * 576 + kc * 8) * 4);
                mma8(acc[0][2 * jj],     af[0], bf);
                mma8(acc[0][2 * jj + 1], af[0], bf + 2);
                mma8(acc[1][2 * jj],     af[1], bf);
                mma8(acc[1][2 * jj + 1], af[1], bf + 2);
            }
        }
        __syncthreads();
    }
    // epilogue: bias + transposed store out[b][c][m]
    #pragma unroll
    for (int mi = 0; mi < 2; mi++) {
        #pragma unroll
        for (int half = 0; half < 2; half++) {
            int m = m0 + wm * 32 + mi * 16 + g + half * 8;
            #pragma unroll
            for (int nj = 0; nj < 8; nj++) {
                #pragma unroll
                for (int e = 0; e < 2; e++) {
                    int col = n0 + wn * 64 + nj * 8 + 2 * q + e;
                    out[((size_t)b * Cc + col) * Nt + m] =
                        acc[mi][nj][half * 2 + e] + bias[col];
                }
            }
        }
    }
}

// ---------------------------------------------------------------------------
extern "C" void kernel_launch(void* const* d_in, const int* in_sizes, int n_in,
                              void* d_out, int out_size)
{
    const float* fv    = (const float*)d_in[0];
    const float* text  = (const float*)d_in[1];
    const float* q_w   = (const float*)d_in[2];
    const float* q_b   = (const float*)d_in[3];
    const float* k_w   = (const float*)d_in[4];
    const float* k_b   = (const float*)d_in[5];
    const float* v_w   = (const float*)d_in[6];
    const float* v_b   = (const float*)d_in[7];
    const float* o_w   = (const float*)d_in[8];
    const float* o_b   = (const float*)d_in[9];
    const float* m1_w  = (const float*)d_in[10];
    const float* m1_b  = (const float*)d_in[11];
    const float* m2_w  = (const float*)d_in[12];
    const float* m2_b  = (const float*)d_in[13];

    const int qproj_smem = 4 * 128 * 40 * 2;                     // 40960
    const int fattn_smem = (256 * 20 + 128 * 40) * 4;            // 40960
    const int oproj_smem = (4 * 128 * 36) * 4;                   // 73728
    cudaFuncSetAttribute(k_qproj, cudaFuncAttributeMaxDynamicSharedMemorySize, qproj_smem);
    cudaFuncSetAttribute(k_fattn, cudaFuncAttributeMaxDynamicSharedMemorySize, fattn_smem);
    cudaFuncSetAttribute(k_oproj, cudaFuncAttributeMaxDynamicSharedMemorySize, oproj_smem);

    // launch order matters: ncu captures launch index 3 -> k_fattn
    dim3 gp(Nt / 32, Cc / 32, Bv);
    k_prep<<<gp, 256>>>(q_w, o_w, fv);                           // 0
    k_text<<<64, 256>>>(text, k_w, k_b, v_w, v_b, m1_w, m1_b, m2_w, m2_b); // 1

    dim3 gq(Nt / 128, Cc / 128, Bv);
    k_qproj<<<gq, 256, qproj_smem>>>(q_b);                       // 2

    dim3 ga(Nt / 128, Bv * NHh);
    k_fattn<<<ga, 256, fattn_smem>>>();                          // 3  <- profiled

    dim3 go(Nt / 128, Cc / 128, Bv);
    k_oproj<<<go, 256, oproj_smem>>>(o_b, (float*)d_out);        // 4
}

// round 8
// speedup vs baseline: 1.5558x; 1.5558x over previous
#include <cuda_runtime.h>
#include <cuda_fp16.h>
#include <math.h>

// Problem constants
#define Bv   2
#define Cc   256
#define Nt   32768      // D*H*W
#define Ss   256
#define TDv  512
#define NHh  8
#define HDd  32
#define SCALE 0.17677669529663687f   // 1/sqrt(32)

// Scratch (device globals — allocation-free rule)
__device__ __half   g_qh[(size_t)Bv * Nt * Cc];     // q post-RoPE, pre-scaled, fp16
__device__ __half   g_attnh[(size_t)Bv * Nt * Cc];  // attention output, fp16
__device__ __half   g_kh[Bv * NHh * Ss * HDd];      // k_rot fp16 [bh][s][d]
__device__ __half   g_vh[Bv * NHh * Ss * HDd];      // pair-interleaved [bh][s2][d][2]
__device__ float2   g_cs[1024];                     // cos/sin table [pos][hd]
__device__ unsigned g_qw[Cc * Cc];                  // q_w tf32-rna [k][n]
__device__ __half   g_owh[Cc * Cc];                 // o_w fp16 TRANSPOSED [n][k]

// ---------------------------------------------------------------------------
// helpers
// ---------------------------------------------------------------------------
__device__ __forceinline__ unsigned f2tf(float f) {
    unsigned r;
    asm("cvt.rna.tf32.f32 %0, %1;" : "=r"(r) : "f"(f));
    return r;
}
__device__ __forceinline__ void mma8(float* d, const unsigned* a, const unsigned* b) {
    asm volatile(
        "mma.sync.aligned.m16n8k8.row.col.f32.tf32.tf32.f32 "
        "{%0,%1,%2,%3}, {%4,%5,%6,%7}, {%8,%9}, {%0,%1,%2,%3};"
        : "+f"(d[0]), "+f"(d[1]), "+f"(d[2]), "+f"(d[3])
        : "r"(a[0]), "r"(a[1]), "r"(a[2]), "r"(a[3]), "r"(b[0]), "r"(b[1]));
}
__device__ __forceinline__ void mma16h(float* d, const unsigned* a, unsigned b0, unsigned b1) {
    asm volatile(
        "mma.sync.aligned.m16n8k16.row.col.f32.f16.f16.f32 "
        "{%0,%1,%2,%3}, {%4,%5,%6,%7}, {%8,%9}, {%0,%1,%2,%3};"
        : "+f"(d[0]), "+f"(d[1]), "+f"(d[2]), "+f"(d[3])
        : "r"(a[0]), "r"(a[1]), "r"(a[2]), "r"(a[3]), "r"(b0), "r"(b1));
}
__device__ __forceinline__ void ldsm4(unsigned* r, unsigned addr) {
    asm volatile("ldmatrix.sync.aligned.m8n8.x4.shared.b16 {%0,%1,%2,%3}, [%4];"
        : "=r"(r[0]), "=r"(r[1]), "=r"(r[2]), "=r"(r[3]) : "r"(addr));
}
__device__ __forceinline__ unsigned packh2(float lo, float hi) {
    __half2 h = __floats2half2_rn(lo, hi);
    return *reinterpret_cast<unsigned*>(&h);
}
__device__ __forceinline__ unsigned saddr(const void* p) {
    return (unsigned)__cvta_generic_to_shared(p);
}
__device__ __forceinline__ void cpa16(unsigned s, const void* g) {
    asm volatile("cp.async.cg.shared.global [%0], [%1], 16;\n" :: "r"(s), "l"(g));
}
#define CPC() asm volatile("cp.async.commit_group;\n" ::)
#define CPW(n) asm volatile("cp.async.wait_group %0;\n" :: "n"(n))

// ---------------------------------------------------------------------------
// Prep: weight conversions + RoPE cos/sin table. grid(256), 256 thr.
// ---------------------------------------------------------------------------
__global__ __launch_bounds__(256) void k_prep(
    const float* __restrict__ qw, const float* __restrict__ ow)
{
    int i = blockIdx.x * 256 + threadIdx.x;    // 65536
    g_qw[i] = f2tf(qw[i]);                     // [k][n] as-is
    int n = i >> 8, k = i & 255;
    g_owh[i] = __float2half(ow[k * 256 + n]);  // transpose to [n][k]

    if (blockIdx.x < 4) {
        int t = blockIdx.x * 256 + threadIdx.x;  // 0..1023
        int pos = t >> 5, hd = t & 31;
        float ex;
        if (hd < 10)       ex = (float)(hd % 5) * 0.2f;
        else if (hd < 20)  ex = (float)((hd - 10) % 5) * 0.2f;
        else               ex = (float)((hd - 20) % 6) * (1.0f / 6.0f);
        float invf = powf(10000.0f, -ex);
        float f = (float)pos * invf;
        float c, s;
        sincosf(f, &s, &c);
        g_cs[t] = make_float2(c, s);
    }
}

// ---------------------------------------------------------------------------
// Text side: 8 tokens per block (64 blocks).
// ---------------------------------------------------------------------------
__global__ __launch_bounds__(256) void k_text(
    const float* __restrict__ text,
    const float* __restrict__ k_w, const float* __restrict__ k_b,
    const float* __restrict__ v_w, const float* __restrict__ v_b,
    const float* __restrict__ m1_w, const float* __restrict__ m1_b,
    const float* __restrict__ m2_w, const float* __restrict__ m2_b)
{
    __shared__ float tx8[8][TDv];
    __shared__ float hbuf8[8][Cc];
    __shared__ float kbuf8[8][Cc];
    const int t0 = blockIdx.x * 8;
    const int b = t0 >> 8;
    const int t = threadIdx.x;

    for (int i = t; i < 8 * TDv; i += 256) {
        int r = i >> 9, c = i & 511;
        tx8[r][c] = text[(size_t)(t0 + r) * TDv + c];
    }
    __syncthreads();

    float kv[8], vv[8], hv[8];
    float kb0 = k_b[t], vb0 = v_b[t], mb0 = m1_b[t];
    #pragma unroll
    for (int r = 0; r < 8; r++) { kv[r] = kb0; vv[r] = vb0; hv[r] = mb0; }

    #pragma unroll 4
    for (int j = 0; j < TDv; j++) {
        float kwj = k_w[j * Cc + t];
        float vwj = v_w[j * Cc + t];
        float mwj = m1_w[j * Cc + t];
        #pragma unroll
        for (int r = 0; r < 8; r++) {
            float x = tx8[r][j];
            kv[r] += x * kwj;
            vv[r] += x * vwj;
            hv[r] += x * mwj;
        }
    }
    const int head = t >> 5, hd = t & 31;
    const int bh = b * NHh + head;
    #pragma unroll
    for (int r = 0; r < 8; r++) {
        hv[r] = 0.5f * hv[r] * (1.0f + erff(hv[r] * 0.70710678118654752f));
        kbuf8[r][t] = kv[r];
        hbuf8[r][t] = hv[r];
        int s = (t0 + r) & 255;
        g_vh[(((size_t)bh * 128 + (s >> 1)) * 32 + hd) * 2 + (s & 1)] = __float2half(vv[r]);
    }
    __syncthreads();

    float ph[8];
    float pb0 = m2_b[t];
    #pragma unroll
    for (int r = 0; r < 8; r++) ph[r] = pb0;
    #pragma unroll 4
    for (int j = 0; j < Cc; j++) {
        float mw = m2_w[j * Cc + t];
        #pragma unroll
        for (int r = 0; r < 8; r++) ph[r] += hbuf8[r][j] * mw;
    }
    #pragma unroll
    for (int r = 0; r < 8; r++) {
        float c, sn;
        sincosf(ph[r], &sn, &c);
        float other = (hd < 16) ? -kbuf8[r][head * 32 + hd + 16]
                                :  kbuf8[r][head * 32 + hd - 16];
        float kr = kv[r] * c + other * sn;
        int s = (t0 + r) & 255;
        g_kh[((size_t)bh * Ss + s) * HDd + hd] = __float2half(kr);
    }
}

// ---------------------------------------------------------------------------
// Q projection (tf32 mma, cp.async double-buffered, R6 form — measured 66us)
// + bias + RoPE + SCALE epilogue, fp16 output.
// ---------------------------------------------------------------------------
__global__ __launch_bounds__(256, 2) void k_qproj(
    const float* __restrict__ fv, const float* __restrict__ bias)
{
    extern __shared__ unsigned smq[];
    unsigned* As = smq;                   // 2 * 32*136
    unsigned* Bs = smq + 2 * 32 * 136;    // 2 * 32*136
    const int b = blockIdx.z;
    const int m0 = blockIdx.x * 128;
    const int n0 = blockIdx.y * 128;
    const int tid = threadIdx.x;
    const int wid = tid >> 5, lane = tid & 31;
    const int q = lane & 3, g = lane >> 2;
    const int wm = wid >> 1, wn = wid & 1;

    float acc[2][8][4];
    #pragma unroll
    for (int a = 0; a < 2; a++)
        #pragma unroll
        for (int j = 0; j < 8; j++)
            #pragma unroll
            for (int r = 0; r < 4; r++) acc[a][j][r] = 0.f;

    const float* A = fv + (size_t)b * Cc * Nt;
    {
        #pragma unroll
        for (int i = 0; i < 4; i++) {
            int c = tid + i * 256;
            int kk = c >> 5, mmc = (c & 31) * 4;
            cpa16(saddr(&As[kk * 136 + mmc]), A + (size_t)kk * Nt + m0 + mmc);
            cpa16(saddr(&Bs[kk * 136 + mmc]), g_qw + kk * Cc + n0 + mmc);
        }
        CPC();
    }
    for (int it = 0; it < 8; it++) {
        if (it < 7) {
            int k0 = (it + 1) * 32;
            unsigned boff = ((it + 1) & 1) * (32 * 136);
            #pragma unroll
            for (int i = 0; i < 4; i++) {
                int c = tid + i * 256;
                int kk = c >> 5, mmc = (c & 31) * 4;
                cpa16(saddr(&As[boff + kk * 136 + mmc]), A + (size_t)(k0 + kk) * Nt + m0 + mmc);
                cpa16(saddr(&Bs[boff + kk * 136 + mmc]), g_qw + (k0 + kk) * Cc + n0 + mmc);
            }
            CPC();
            CPW(1);
        } else {
            CPW(0);
        }
        __syncthreads();
        const unsigned* as = As + (it & 1) * (32 * 136);
        const unsigned* bs = Bs + (it & 1) * (32 * 136);
        #pragma unroll
        for (int kc = 0; kc < 4; kc++) {
            unsigned af[2][4];
            #pragma unroll
            for (int mi = 0; mi < 2; mi++) {
                int row = wm * 32 + mi * 16 + g;
                af[mi][0] = as[(kc * 8 + q) * 136 + row];
                af[mi][1] = as[(kc * 8 + q) * 136 + row + 8];
                af[mi][2] = as[(kc * 8 + q + 4) * 136 + row];
                af[mi][3] = as[(kc * 8 + q + 4) * 136 + row + 8];
            }
            #pragma unroll
            for (int nj = 0; nj < 8; nj++) {
                int col = wn * 64 + nj * 8 + g;
                unsigned bf[2];
                bf[0] = bs[(kc * 8 + q) * 136 + col];
                bf[1] = bs[(kc * 8 + q + 4) * 136 + col];
                mma8(acc[0][nj], af[0], bf);
                mma8(acc[1][nj], af[1], bf);
            }
        }
        __syncthreads();
    }
    // stage cos/sin table into now-dead smem
    float2* css = (float2*)smq;
    for (int i = tid; i < 1024; i += 256) css[i] = g_cs[i];
    __syncthreads();
    // epilogue: bias + RoPE + SCALE + fp16 store
    unsigned* qo = (unsigned*)g_qh;
    #pragma unroll
    for (int mi = 0; mi < 2; mi++) {
        #pragma unroll
        for (int half = 0; half < 2; half++) {
            int m = m0 + wm * 32 + mi * 16 + g + half * 8;
            int d = m >> 10, hh = (m >> 5) & 31, wc = m & 31;
            float vals[8][2];
            #pragma unroll
            for (int nj = 0; nj < 8; nj++) {
                int col = n0 + wn * 64 + nj * 8 + 2 * q;
                vals[nj][0] = acc[mi][nj][half * 2 + 0] + bias[col];
                vals[nj][1] = acc[mi][nj][half * 2 + 1] + bias[col + 1];
            }
            unsigned* orow = qo + ((size_t)b * Nt + m) * (Cc / 2);
            #pragma unroll
            for (int nj = 0; nj < 8; nj++) {
                float o2[2];
                #pragma unroll
                for (int e = 0; e < 2; e++) {
                    int hd = (nj & 3) * 8 + 2 * q + e;
                    bool lo = hd < 16;
                    int pos = lo ? ((hd < 10) ? d : hh) : ((hd < 20) ? hh : wc);
                    float2 cs = css[pos * 32 + hd];
                    float partner = lo ? vals[nj + 2][e] : vals[nj - 2][e];
                    float r = lo ? vals[nj][e] * cs.x - partner * cs.y
                                 : vals[nj][e] * cs.x + partner * cs.y;
                    o2[e] = r * SCALE;
                }
                int col = n0 + wn * 64 + nj * 8 + 2 * q;
                orow[col >> 1] = packh2(o2[0], o2[1]);
            }
        }
    }
}

// ---------------------------------------------------------------------------
// Fused attention, all-fp16. QK K-frags via ldmatrix.x4; occupancy 4.
// Ksh [s 256][d2 20] half2; Vs [s2 128][d 40] half2. fp16 output.
// ---------------------------------------------------------------------------
__global__ __launch_bounds__(256, 4) void k_fattn() {
    extern __shared__ unsigned sm[];
    unsigned* Ksh = sm;                // 256*20
    unsigned* Vs  = sm + 256 * 20;     // 128*40
    const int bh = blockIdx.y;
    const int b = bh >> 3, h = bh & 7;
    const int m0 = blockIdx.x * 128;
    const int tid = threadIdx.x, wid = tid >> 5, lane = tid & 31;
    const int q = lane & 3, g = lane >> 2;

    const unsigned* kph = (const unsigned*)g_kh + (size_t)bh * 256 * 16;
    const unsigned* vph = (const unsigned*)g_vh + (size_t)bh * 128 * 32;
    for (int i = tid; i < 256 * 16; i += 256) {
        int s = i >> 4, d2 = i & 15;
        Ksh[s * 20 + d2] = kph[i];
    }
    for (int i = tid; i < 128 * 32; i += 256) {
        int s2 = i >> 5, d = i & 31;
        Vs[s2 * 40 + d] = vph[i];
    }
    // per-lane ldmatrix base: lane -> row key=(lane&7), 16B-chunk = lane>>3
    const unsigned kq_lane = saddr(Ksh) + ((lane & 7) * 20 + (lane >> 3) * 4) * 4;

    const unsigned* qrow = (const unsigned*)g_qh
                         + ((size_t)b * Nt + m0 + wid * 16) * (Cc / 2) + h * 16;
    unsigned qf[2][4];
    #pragma unroll
    for (int ks = 0; ks < 2; ks++) {
        qf[ks][0] = qrow[(size_t)g * 128 + ks * 8 + q];
        qf[ks][1] = qrow[(size_t)(g + 8) * 128 + ks * 8 + q];
        qf[ks][2] = qrow[(size_t)g * 128 + ks * 8 + q + 4];
        qf[ks][3] = qrow[(size_t)(g + 8) * 128 + ks * 8 + q + 4];
    }
    __syncthreads();

    float o[4][4];
    #pragma unroll
    for (int i = 0; i < 4; i++)
        #pragma unroll
        for (int r = 0; r < 4; r++) o[i][r] = 0.f;
    float l_lo = 0.f, l_hi = 0.f;

    #pragma unroll
    for (int ch = 0; ch < 8; ch++) {
        float s[4][4];
        #pragma unroll
        for (int t = 0; t < 4; t++)
            #pragma unroll
            for (int r = 0; r < 4; r++) s[t][r] = 0.f;
        #pragma unroll
        for (int nt = 0; nt < 4; nt++) {
            unsigned bf[4];                    // tiles d[0:8),[8:16),[16:24),[24:32)
            ldsm4(bf, kq_lane + (ch * 32 + nt * 8) * 80);
            mma16h(s[nt], qf[0], bf[0], bf[1]);
            mma16h(s[nt], qf[1], bf[2], bf[3]);
        }
        unsigned pa[4][2];
        #pragma unroll
        for (int st = 0; st < 4; st++) {
            float e0 = __expf(s[st][0]), e1 = __expf(s[st][1]);
            float e2 = __expf(s[st][2]), e3 = __expf(s[st][3]);
            l_lo += e0 + e1;
            l_hi += e2 + e3;
            pa[st][0] = packh2(e0, e1);
            pa[st][1] = packh2(e2, e3);
        }
        #pragma unroll
        for (int kt = 0; kt < 2; kt++) {
            unsigned Af[4] = { pa[2 * kt][0], pa[2 * kt][1],
                               pa[2 * kt + 1][0], pa[2 * kt + 1][1] };
            int s2b = ch * 16 + kt * 8 + q;
            #pragma unroll
            for (int nt = 0; nt < 4; nt++) {
                mma16h(o[nt], Af, Vs[s2b * 40 + nt * 8 + g],
                                  Vs[(s2b + 4) * 40 + nt * 8 + g]);
            }
        }
    }
    l_lo += __shfl_xor_sync(0xffffffffu, l_lo, 1);
    l_lo += __shfl_xor_sync(0xffffffffu, l_lo, 2);
    l_hi += __shfl_xor_sync(0xffffffffu, l_hi, 1);
    l_hi += __shfl_xor_sync(0xffffffffu, l_hi, 2);
    float il = 1.0f / l_lo, ih = 1.0f / l_hi;

    unsigned* op  = (unsigned*)g_attnh
                  + ((size_t)b * Nt + m0 + wid * 16 + g) * (Cc / 2) + h * 16;
    unsigned* op2 = op + 8 * (Cc / 2);
    #pragma unroll
    for (int nt = 0; nt < 4; nt++) {
        op [nt * 4 + q] = packh2(o[nt][0] * il, o[nt][1] * il);
        op2[nt * 4 + q] = packh2(o[nt][2] * ih, o[nt][3] * ih);
    }
}

// ---------------------------------------------------------------------------
// O projection: FP16 mma, cp.async double-buffered, bias + transposed store.
// As/Bs: [row 128][k 40 halves pad] per buffer.
// ---------------------------------------------------------------------------
__global__ __launch_bounds__(256, 3) void k_oproj(
    const float* __restrict__ bias, float* __restrict__ out)
{
    extern __shared__ __half smoh[];
    // As buf0 | As buf1 | Bs buf0 | Bs buf1, each 128*40 halves (5120)
    const int b = blockIdx.z;
    const int m0 = blockIdx.x * 128;
    const int n0 = blockIdx.y * 128;
    const int tid = threadIdx.x;
    const int wid = tid >> 5, lane = tid & 31;
    const int q = lane & 3, g = lane >> 2;
    const int wm = wid >> 1, wn = wid & 1;

    float acc[2][8][4];
    #pragma unroll
    for (int a = 0; a < 2; a++)
        #pragma unroll
        for (int j = 0; j < 8; j++)
            #pragma unroll
            for (int r = 0; r < 4; r++) acc[a][j][r] = 0.f;

    const __half* Ag = g_attnh + ((size_t)b * Nt + m0) * Cc;
    const __half* Bg = g_owh + (size_t)n0 * Cc;
    {
        #pragma unroll
        for (int i = 0; i < 2; i++) {
            int c = tid + i * 256;
            int row = c >> 2, off = (c & 3) * 8;
            cpa16(saddr(smoh + row * 40 + off), Ag + (size_t)row * Cc + off);
            cpa16(saddr(smoh + 10240 + row * 40 + off), Bg + (size_t)row * Cc + off);
        }
        CPC();
    }
    for (int it = 0; it < 8; it++) {
        if (it < 7) {
            int k0 = (it + 1) * 32;
            int buf = (it + 1) & 1;
            #pragma unroll
            for (int i = 0; i < 2; i++) {
                int c = tid + i * 256;
                int row = c >> 2, off = (c & 3) * 8;
                cpa16(saddr(smoh + buf * 5120 + row * 40 + off),
                      Ag + (size_t)row * Cc + k0 + off);
                cpa16(saddr(smoh + 10240 + buf * 5120 + row * 40 + off),
                      Bg + (size_t)row * Cc + k0 + off);
            }
            CPC();
            CPW(1);
        } else {
            CPW(0);
        }
        __syncthreads();
        const unsigned* as32 = (const unsigned*)(smoh + (it & 1) * 5120);
        const unsigned* bs32 = (const unsigned*)(smoh + 10240 + (it & 1) * 5120);
        #pragma unroll
        for (int kc = 0; kc < 2; kc++) {
            unsigned af[2][4];
            #pragma unroll
            for (int mi = 0; mi < 2; mi++) {
                int row = wm * 32 + mi * 16 + g;
                af[mi][0] = as32[row * 20 + kc * 8 + q];
                af[mi][1] = as32[(row + 8) * 20 + kc * 8 + q];
                af[mi][2] = as32[row * 20 + kc * 8 + q + 4];
                af[mi][3] = as32[(row + 8) * 20 + kc * 8 + q + 4];
            }
            #pragma unroll
            for (int nj = 0; nj < 8; nj++) {
                int col = wn * 64 + nj * 8 + g;
                unsigned b0 = bs32[col * 20 + kc * 8 + q];
                unsigned b1 = bs32[col * 20 + kc * 8 + q + 4];
                mma16h(acc[0][nj], af[0], b0, b1);
                mma16h(acc[1][nj], af[1], b0, b1);
            }
        }
        __syncthreads();
    }
    // epilogue: bias + transposed store out[b][c][m]
    #pragma unroll
    for (int mi = 0; mi < 2; mi++) {
        #pragma unroll
        for (int half = 0; half < 2; half++) {
            int m = m0 + wm * 32 + mi * 16 + g + half * 8;
            #pragma unroll
            for (int nj = 0; nj < 8; nj++) {
                #pragma unroll
                for (int e = 0; e < 2; e++) {
                    int col = n0 + wn * 64 + nj * 8 + 2 * q + e;
                    out[((size_t)b * Cc + col) * Nt + m] =
                        acc[mi][nj][half * 2 + e] + bias[col];
                }
            }
        }
    }
}

// ---------------------------------------------------------------------------
extern "C" void kernel_launch(void* const* d_in, const int* in_sizes, int n_in,
                              void* d_out, int out_size)
{
    const float* fv    = (const float*)d_in[0];
    const float* text  = (const float*)d_in[1];
    const float* q_w   = (const float*)d_in[2];
    const float* q_b   = (const float*)d_in[3];
    const float* k_w   = (const float*)d_in[4];
    const float* k_b   = (const float*)d_in[5];
    const float* v_w   = (const float*)d_in[6];
    const float* v_b   = (const float*)d_in[7];
    const float* o_w   = (const float*)d_in[8];
    const float* o_b   = (const float*)d_in[9];
    const float* m1_w  = (const float*)d_in[10];
    const float* m1_b  = (const float*)d_in[11];
    const float* m2_w  = (const float*)d_in[12];
    const float* m2_b  = (const float*)d_in[13];

    const int qproj_smem = (4 * 32 * 136) * 4;                   // 69632
    const int fattn_smem = (256 * 20 + 128 * 40) * 4;            // 40960
    const int oproj_smem = 4 * 128 * 40 * 2;                     // 40960
    cudaFuncSetAttribute(k_qproj, cudaFuncAttributeMaxDynamicSharedMemorySize, qproj_smem);
    cudaFuncSetAttribute(k_fattn, cudaFuncAttributeMaxDynamicSharedMemorySize, fattn_smem);
    cudaFuncSetAttribute(k_oproj, cudaFuncAttributeMaxDynamicSharedMemorySize, oproj_smem);

    // launch order: ncu captures launch index 3 -> k_fattn
    k_prep<<<256, 256>>>(q_w, o_w);                              // 0
    k_text<<<64, 256>>>(text, k_w, k_b, v_w, v_b, m1_w, m1_b, m2_w, m2_b); // 1

    dim3 gq(Nt / 128, Cc / 128, Bv);
    k_qproj<<<gq, 256, qproj_smem>>>(fv, q_b);                   // 2

    dim3 ga(Nt / 128, Bv * NHh);
    k_fattn<<<ga, 256, fattn_smem>>>();                          // 3  <- profiled

    dim3 go(Nt / 128, Cc / 128, Bv);
    k_oproj<<<go, 256, oproj_smem>>>(o_b, (float*)d_out);        // 4
}